// round 13
// baseline (speedup 1.0000x reference)
#include <cuda_runtime.h>
#include <cstddef>
#include <cstdint>

// ContrastMemory for GB300 — row-inverted gather; copy driven by the async
// bulk-copy engine (cp.async.bulk), dot machine reads staged rows from SMEM.
// Pipeline: 3 x 8-row chunks per block; bulk-in (DRAM->SMEM) -> dots (SMEM)
// -> bulk-out (SMEM->DRAM), all engine traffic off the warp issue path.
// d_out layout (float32):
//   [0, H)          out_v1   = exp((memory_v2[idx] . v1)/T) / Z_v1
//   [H, 2H)         out_v2   = exp((memory_v1[idx] . v2)/T) / Z_v2
//   [2H, 2H+ND)     new_memory_v1
//   [2H+ND, 2H+2ND) new_memory_v2

#define T_INV 14.2857142857142857f   // 1/0.07
#define MOM   0.5f

#define MAX_N   100000
#define CAP     32
#define MAX_OVF 16384

#define NBLK      1184     // main grid
#define CH        8        // rows per chunk
#define BANKB     (CH*512) // bytes per bank per chunk = 4096
#define BUFB      (2*BANKB)

// State invariant: d_count[0..N), d_ovf_cnt are ZERO at kernel_launch entry
// (zero-init at load; finish_kernel re-zeroes them). g_sum is zeroed by
// build_kernel before main_kernel accumulates.
__device__ int    d_count[MAX_N];
__device__ int    d_ell[(size_t)MAX_N * CAP];   // packed (b<<13)|k ; row stride 128B
__device__ int    d_ovf[MAX_OVF];
__device__ int    d_ovf_cnt;
__device__ double g_sum[2];                     // [0]: out_v1 raw sum, [1]: out_v2

// ---------------- PTX helpers ----------------
__device__ __forceinline__ uint32_t smem_u32(const void* p) {
    return (uint32_t)__cvta_generic_to_shared(p);
}
__device__ __forceinline__ void mbar_init(uint32_t a, uint32_t cntarr) {
    asm volatile("mbarrier.init.shared.b64 [%0], %1;" :: "r"(a), "r"(cntarr) : "memory");
}
__device__ __forceinline__ void mbar_expect(uint32_t a, uint32_t tx) {
    asm volatile("mbarrier.arrive.expect_tx.shared.b64 _, [%0], %1;"
                 :: "r"(a), "r"(tx) : "memory");
}
__device__ __forceinline__ void mbar_wait(uint32_t a, uint32_t ph) {
    uint32_t done = 0;
    while (!done) {
        asm volatile("{\n\t.reg .pred p;\n\t"
                     "mbarrier.try_wait.parity.acquire.cta.shared::cta.b64 p, [%1], %2, 0x989680;\n\t"
                     "selp.b32 %0, 1, 0, p;\n\t}"
                     : "=r"(done) : "r"(a), "r"(ph) : "memory");
    }
}
__device__ __forceinline__ void bulk_in(uint32_t smem, const void* gmem,
                                        uint32_t bytes, uint32_t mbar) {
    asm volatile("cp.async.bulk.shared::cluster.global.mbarrier::complete_tx::bytes "
                 "[%0], [%1], %2, [%3];"
                 :: "r"(smem), "l"(gmem), "r"(bytes), "r"(mbar) : "memory");
}
__device__ __forceinline__ void bulk_out(void* gmem, uint32_t smem, uint32_t bytes) {
    asm volatile("cp.async.bulk.global.shared::cta.bulk_group [%0], [%1], %2;"
                 :: "l"(gmem), "r"(smem), "r"(bytes) : "memory");
}
#define BULK_COMMIT() asm volatile("cp.async.bulk.commit_group;" ::: "memory")
#define BULK_WAIT(n)  asm volatile("cp.async.bulk.wait_group %0;" :: "n"(n) : "memory")

// k1: counting-sort of the shared index set into ELL rows (~10 us).
__global__ void __launch_bounds__(256) build_kernel(
        const int* __restrict__ idx, int H, int KP1, float invKP1)
{
    const int i = blockIdx.x * blockDim.x + threadIdx.x;
    if (i == 0) { g_sum[0] = 0.0; g_sum[1] = 0.0; }
    if (i >= H) return;

    const int r = __ldg(&idx[i]);
    int b = __float2int_rz(__int2float_rn(i) * invKP1);
    int k = i - b * KP1;
    if (k < 0)         { b--; k += KP1; }
    else if (k >= KP1) { b++; k -= KP1; }

    const int packed = (b << 13) | k;
    const int pos = atomicAdd(&d_count[r], 1);
    if (pos < CAP) {
        d_ell[(size_t)r * CAP + pos] = packed;
    } else {
        const int o = atomicAdd(&d_ovf_cnt, 1);
        if (o < MAX_OVF) d_ovf[o] = packed;
    }
}

// k2: bulk-engine copy pipeline + SMEM-fed dot machine.
__global__ void __launch_bounds__(256) main_kernel(
        const float4* __restrict__ v1,
        const float4* __restrict__ v2,
        const int*    __restrict__ idx,
        const float4* __restrict__ mem1f,
        const float4* __restrict__ mem2f,
        float* __restrict__ out,
        int N, int H, int KP1)
{
    __shared__ __align__(128) unsigned char sbuf[3][BUFB];
    __shared__ uint64_t mb[3];

    const int tid         = threadIdx.x;
    const int warpInBlock = tid >> 5;
    const int lane        = tid & 31;

    const char* mem1 = (const char*)mem1f;
    const char* mem2 = (const char*)mem2f;
    // output bank bases, derived from out
    char* outmem1 = (char*)(out + 2 * (size_t)H);
    char* outmem2 = outmem1 + (size_t)N * 512;

    // contiguous row range for this block
    const int rowsBase = N / NBLK;
    const int rem      = N % NBLK;
    const int rs    = blockIdx.x * rowsBase + min((int)blockIdx.x, rem);
    const int nrows = rowsBase + ((int)blockIdx.x < rem);
    const int nch   = (nrows + CH - 1) / CH;

    const uint32_t sb0 = smem_u32(&sbuf[0][0]);
    const uint32_t mb0 = smem_u32(&mb[0]);

    if (tid == 0) {
        mbar_init(mb0,      1);
        mbar_init(mb0 + 8,  1);
        mbar_init(mb0 + 16, 1);
    }
    __syncthreads();

    // lane's result slot for the quad reduction
    const int q  = ((lane >> 4) & 1) | (((lane >> 3) & 1) << 1) | (((lane >> 2) & 1) << 2);
    const int qe = q >> 1;
    const int qo = q & 1;
    const bool rep = ((lane & 3) == 0);

    float local0 = 0.0f, local1 = 0.0f;

    // prologue: fill pipeline with chunks 0 and 1
    if (tid == 0) {
        for (int c = 0; c < 2 && c < nch; ++c) {
            const int cs   = rs + c * CH;
            const int rows = min(CH, rs + nrows - cs);
            const uint32_t bytes = rows * 512;
            const int buf = c % 3;
            mbar_expect(mb0 + buf * 8, 2 * bytes);
            bulk_in(sb0 + buf * BUFB,         mem1 + (size_t)cs * 512, bytes, mb0 + buf * 8);
            bulk_in(sb0 + buf * BUFB + BANKB, mem2 + (size_t)cs * 512, bytes, mb0 + buf * 8);
        }
    }

    for (int c = 0; c < nch; ++c) {
        const int buf  = c % 3;
        const int cs   = rs + c * CH;
        const int rows = min(CH, rs + nrows - cs);
        const uint32_t bytes = rows * 512;

        mbar_wait(mb0 + buf * 8, (uint32_t)((c / 3) & 1));

        // one warp per staged row
        if (warpInBlock < rows) {
            const int lr = warpInBlock;
            const int r  = cs + lr;
            const int cnt = min(d_count[r], CAP);
            if (cnt > 0) {
                const float4 m1 = *(const float4*)(&sbuf[buf][lr * 512 + lane * 16]);
                const float4 m2 = *(const float4*)(&sbuf[buf][BANKB + lr * 512 + lane * 16]);

                for (int j = 0; j < cnt; j += 4) {
                    const int4 pk = *reinterpret_cast<const int4*>(
                                        &d_ell[(size_t)r * CAP + j]);

                    float v0, v1p, v2p, v3, v4p, v5, v6, v7;
                    {
                        const int b = pk.x >> 13;
                        const float4 x1 = __ldg(&v1[(size_t)b * 32 + lane]);
                        const float4 x2 = __ldg(&v2[(size_t)b * 32 + lane]);
                        v0  = m2.x * x1.x + m2.y * x1.y + m2.z * x1.z + m2.w * x1.w;
                        v1p = m1.x * x2.x + m1.y * x2.y + m1.z * x2.z + m1.w * x2.w;
                    }
                    {
                        const int b = ((j + 1 < cnt) ? pk.y : pk.x) >> 13;
                        const float4 x1 = __ldg(&v1[(size_t)b * 32 + lane]);
                        const float4 x2 = __ldg(&v2[(size_t)b * 32 + lane]);
                        v2p = m2.x * x1.x + m2.y * x1.y + m2.z * x1.z + m2.w * x1.w;
                        v3  = m1.x * x2.x + m1.y * x2.y + m1.z * x2.z + m1.w * x2.w;
                    }
                    {
                        const int b = ((j + 2 < cnt) ? pk.z : pk.x) >> 13;
                        const float4 x1 = __ldg(&v1[(size_t)b * 32 + lane]);
                        const float4 x2 = __ldg(&v2[(size_t)b * 32 + lane]);
                        v4p = m2.x * x1.x + m2.y * x1.y + m2.z * x1.z + m2.w * x1.w;
                        v5  = m1.x * x2.x + m1.y * x2.y + m1.z * x2.z + m1.w * x2.w;
                    }
                    {
                        const int b = ((j + 3 < cnt) ? pk.w : pk.x) >> 13;
                        const float4 x1 = __ldg(&v1[(size_t)b * 32 + lane]);
                        const float4 x2 = __ldg(&v2[(size_t)b * 32 + lane]);
                        v6  = m2.x * x1.x + m2.y * x1.y + m2.z * x1.z + m2.w * x1.w;
                        v7  = m1.x * x2.x + m1.y * x2.y + m1.z * x2.z + m1.w * x2.w;
                    }

                    // 8-value pack-and-butterfly: 16 SHFL + 7 SEL
                    v0  += __shfl_xor_sync(0xffffffffu, v0,  16);
                    v1p += __shfl_xor_sync(0xffffffffu, v1p, 16);
                    v2p += __shfl_xor_sync(0xffffffffu, v2p, 16);
                    v3  += __shfl_xor_sync(0xffffffffu, v3,  16);
                    v4p += __shfl_xor_sync(0xffffffffu, v4p, 16);
                    v5  += __shfl_xor_sync(0xffffffffu, v5,  16);
                    v6  += __shfl_xor_sync(0xffffffffu, v6,  16);
                    v7  += __shfl_xor_sync(0xffffffffu, v7,  16);

                    float w0 = (lane & 16) ? v1p : v0;
                    float w1 = (lane & 16) ? v3  : v2p;
                    float w2 = (lane & 16) ? v5  : v4p;
                    float w3 = (lane & 16) ? v7  : v6;
                    w0 += __shfl_xor_sync(0xffffffffu, w0, 8);
                    w1 += __shfl_xor_sync(0xffffffffu, w1, 8);
                    w2 += __shfl_xor_sync(0xffffffffu, w2, 8);
                    w3 += __shfl_xor_sync(0xffffffffu, w3, 8);

                    float u0 = (lane & 8) ? w1 : w0;
                    float u1 = (lane & 8) ? w3 : w2;
                    u0 += __shfl_xor_sync(0xffffffffu, u0, 4);
                    u1 += __shfl_xor_sync(0xffffffffu, u1, 4);

                    float t = (lane & 4) ? u1 : u0;
                    t += __shfl_xor_sync(0xffffffffu, t, 2);
                    t += __shfl_xor_sync(0xffffffffu, t, 1);

                    const float ex = __expf(t * T_INV);

                    if (rep && (j + qe) < cnt) {
                        const int p  = (qe == 0) ? pk.x : (qe == 1) ? pk.y
                                     : (qe == 2) ? pk.z : pk.w;
                        const int d2 = (p >> 13) * KP1 + (p & 8191);
                        __stcs(&out[qo ? (H + d2) : d2], ex);
                        if (qo) local1 += ex; else local0 += ex;
                    }
                }
            }
        }
        __syncthreads();   // all dots on this chunk done reading sbuf[buf]

        if (tid == 0) {
            // engine store-out of the staged chunk
            bulk_out(outmem1 + (size_t)cs * 512, sb0 + buf * BUFB,         bytes);
            bulk_out(outmem2 + (size_t)cs * 512, sb0 + buf * BUFB + BANKB, bytes);
            BULK_COMMIT();
            // refill the pipeline: chunk c+2 reuses buffer (c+2)%3 = (c-1)%3,
            // whose bulk-out was committed last iteration -> allow 1 pending.
            const int cn = c + 2;
            if (cn < nch) {
                BULK_WAIT(1);
                const int cs2   = rs + cn * CH;
                const int rows2 = min(CH, rs + nrows - cs2);
                const uint32_t bytes2 = rows2 * 512;
                const int buf2 = cn % 3;
                mbar_expect(mb0 + buf2 * 8, 2 * bytes2);
                bulk_in(sb0 + buf2 * BUFB,         mem1 + (size_t)cs2 * 512, bytes2, mb0 + buf2 * 8);
                bulk_in(sb0 + buf2 * BUFB + BANKB, mem2 + (size_t)cs2 * 512, bytes2, mb0 + buf2 * 8);
            }
        }
    }

    if (tid == 0) BULK_WAIT(0);   // all engine stores complete before exit

    // overflow entries (expected: none) — direct full-warp gather path
    const int gwarp      = blockIdx.x * 8 + warpInBlock;
    const int totalWarps = NBLK * 8;
    const int novf = min(d_ovf_cnt, MAX_OVF);
    for (int o = gwarp; o < novf; o += totalWarps) {
        const int p  = d_ovf[o];
        const int b  = p >> 13;
        const int d2 = b * KP1 + (p & 8191);
        const int rr = __ldg(&idx[d2]);

        const float4 a1 = mem1f[(size_t)rr * 32 + lane];
        const float4 a2 = mem2f[(size_t)rr * 32 + lane];
        const float4 x1 = __ldg(&v1[(size_t)b * 32 + lane]);
        const float4 x2 = __ldg(&v2[(size_t)b * 32 + lane]);

        float s1 = a1.x * x2.x + a1.y * x2.y + a1.z * x2.z + a1.w * x2.w;
        float s2 = a2.x * x1.x + a2.y * x1.y + a2.z * x1.z + a2.w * x1.w;
        #pragma unroll
        for (int qq = 16; qq > 0; qq >>= 1) {
            s1 += __shfl_xor_sync(0xffffffffu, s1, qq);
            s2 += __shfl_xor_sync(0xffffffffu, s2, qq);
        }
        if (lane == 0) {
            const float e2 = __expf(s2 * T_INV);
            const float e1 = __expf(s1 * T_INV);
            __stcs(&out[d2], e2);
            __stcs(&out[H + d2], e1);
            local0 += e2;
            local1 += e1;
        }
    }

    // block reduce -> one double atomic per block per half
    #pragma unroll
    for (int o = 16; o > 0; o >>= 1) {
        local0 += __shfl_xor_sync(0xffffffffu, local0, o);
        local1 += __shfl_xor_sync(0xffffffffu, local1, o);
    }
    __shared__ float sh0[8], sh1[8];
    if (lane == 0) { sh0[warpInBlock] = local0; sh1[warpInBlock] = local1; }
    __syncthreads();
    if (tid == 0) {
        float a = 0.0f, b = 0.0f;
        for (int w = 0; w < 8; ++w) { a += sh0[w]; b += sh1[w]; }
        atomicAdd(&g_sum[0], (double)a);
        atomicAdd(&g_sum[1], (double)b);
    }
}

// k3: lean finish — grid-stride scale, momentum update, state re-zero.
#define FIN_SCALE_BLOCKS 444
#define FIN_ZERO_BLOCKS  128
__global__ void __launch_bounds__(256) finish_kernel(
        float4* __restrict__ out4,
        int Hv2, int Hv,
        int H, long long Nll, int N,
        const float* __restrict__ v1,
        const float* __restrict__ v2,
        const float* __restrict__ mem1,
        const float* __restrict__ mem2,
        const int*   __restrict__ y,
        float* __restrict__ outmem1,
        float* __restrict__ outmem2,
        int B)
{
    const int bx = (int)blockIdx.x;

    if (bx < FIN_SCALE_BLOCKS) {
        const int stride = FIN_SCALE_BLOCKS * blockDim.x;
        const float sc0 = (float)((double)H / (g_sum[0] * (double)Nll));
        const float sc1 = (float)((double)H / (g_sum[1] * (double)Nll));
        for (int i = bx * blockDim.x + threadIdx.x; i < Hv2; i += stride) {
            const float scale = (i < Hv) ? sc0 : sc1;
            float4 v = out4[i];
            v.x *= scale; v.y *= scale; v.z *= scale; v.w *= scale;
            out4[i] = v;
        }
        return;
    }

    if (bx < FIN_SCALE_BLOCKS + B) {
        const int ub    = bx - FIN_SCALE_BLOCKS;
        const int which = threadIdx.x >> 7;
        const int t     = threadIdx.x & 127;
        const int lane  = threadIdx.x & 31;
        const int w128  = (threadIdx.x >> 5) & 3;

        const float* v      = which ? v2      : v1;
        const float* mem    = which ? mem2    : mem1;
        float*       outmem = which ? outmem2 : outmem1;

        const int row = __ldg(&y[ub]);
        const float u = MOM * mem[(size_t)row * 128 + t] + (1.0f - MOM) * v[(size_t)ub * 128 + t];

        float ss = u * u;
        #pragma unroll
        for (int o = 16; o > 0; o >>= 1)
            ss += __shfl_xor_sync(0xffffffffu, ss, o);

        __shared__ float sh[2][4];
        if (lane == 0) sh[which][w128] = ss;
        __syncthreads();

        const float tot = sh[which][0] + sh[which][1] + sh[which][2] + sh[which][3];
        outmem[(size_t)row * 128 + t] = u * rsqrtf(tot);
        return;
    }

    const int zb = bx - FIN_SCALE_BLOCKS - B;
    const int zstride = FIN_ZERO_BLOCKS * blockDim.x;
    for (int i = zb * blockDim.x + threadIdx.x; i < N; i += zstride)
        d_count[i] = 0;
    if (zb == 0 && threadIdx.x == 0) d_ovf_cnt = 0;
}

extern "C" void kernel_launch(void* const* d_in, const int* in_sizes, int n_in,
                              void* d_out, int out_size)
{
    const float* v1   = (const float*)d_in[0];
    const float* v2   = (const float*)d_in[1];
    const int*   idx  = (const int*)  d_in[2];
    const int*   y    = (const int*)  d_in[3];
    const float* mem1 = (const float*)d_in[4];
    const float* mem2 = (const float*)d_in[5];

    const int B   = in_sizes[3];          // 128
    const int D   = in_sizes[0] / B;      // 128
    const int KP1 = in_sizes[2] / B;      // 4097
    const int N   = in_sizes[4] / D;      // 100000
    const int H   = B * KP1;              // 524416
    const int ND  = N * D;                // 12800000

    float* out = (float*)d_out;
    float* outmem1 = out + 2 * (size_t)H;
    float* outmem2 = outmem1 + (size_t)ND;

    const float invKP1 = 1.0f / (float)KP1;

    build_kernel<<<(H + 255) / 256, 256>>>(idx, H, KP1, invKP1);

    main_kernel<<<NBLK, 256>>>((const float4*)v1, (const float4*)v2, idx,
                               (const float4*)mem1, (const float4*)mem2,
                               out, N, H, KP1);

    const int Hv  = H / 4;
    const int Hv2 = 2 * Hv;
    finish_kernel<<<FIN_SCALE_BLOCKS + B + FIN_ZERO_BLOCKS, 256>>>(
        (float4*)d_out, Hv2, Hv, H, (long long)N, N,
        v1, v2, mem1, mem2, y, outmem1, outmem2, B);
}

// round 14
// speedup vs baseline: 1.2607x; 1.2607x over previous
#include <cuda_runtime.h>
#include <cstddef>

// ContrastMemory for GB300 — row-inverted gather; copy fused into main
// (each bank row is read from DRAM exactly once). Main capped at 64 regs
// (4 blocks/SM) for latency hiding; batched 8-value warp reduction.
// d_out layout (float32):
//   [0, H)          out_v1   = exp((memory_v2[idx] . v1)/T) / Z_v1
//   [H, 2H)         out_v2   = exp((memory_v1[idx] . v2)/T) / Z_v2
//   [2H, 2H+ND)     new_memory_v1
//   [2H+ND, 2H+2ND) new_memory_v2

#define T_INV 14.2857142857142857f   // 1/0.07
#define MOM   0.5f

#define MAX_N   100000
#define CAP     32
#define MAX_OVF 16384

// State invariant: d_count[0..N), d_ovf_cnt are ZERO at kernel_launch entry
// (zero-init at load; finish_kernel re-zeroes them). g_sum is zeroed by
// build_kernel before main_kernel accumulates.
__device__ int    d_count[MAX_N];
__device__ int    d_ell[(size_t)MAX_N * CAP];   // packed (b<<13)|k ; row stride 128B
__device__ int    d_ovf[MAX_OVF];
__device__ int    d_ovf_cnt;
__device__ double g_sum[2];                     // [0]: out_v1 raw sum, [1]: out_v2

// k1: counting-sort of the shared index set into ELL rows (~10 us).
__global__ void __launch_bounds__(256) build_kernel(
        const int* __restrict__ idx, int H, int KP1, float invKP1)
{
    const int i = blockIdx.x * blockDim.x + threadIdx.x;
    if (i == 0) { g_sum[0] = 0.0; g_sum[1] = 0.0; }
    if (i >= H) return;

    const int r = __ldg(&idx[i]);
    int b = __float2int_rz(__int2float_rn(i) * invKP1);
    int k = i - b * KP1;
    if (k < 0)         { b--; k += KP1; }
    else if (k >= KP1) { b++; k -= KP1; }

    const int packed = (b << 13) | k;
    const int pos = atomicAdd(&d_count[r], 1);
    if (pos < CAP) {
        d_ell[(size_t)r * CAP + pos] = packed;
    } else {
        const int o = atomicAdd(&d_ovf_cnt, 1);
        if (o < MAX_OVF) d_ovf[o] = packed;
    }
}

// k2: one warp per bank row; row pair in registers; copy-through fused;
// entries processed 4 at a time (8-value pack-and-butterfly reduction).
// Reg-capped to 64 (4 blocks/SM -> 32 warps/SM) for latency hiding.
__global__ void __launch_bounds__(256, 4) main_kernel(
        const float4* __restrict__ v1,
        const float4* __restrict__ v2,
        const int*    __restrict__ idx,
        const float4* __restrict__ mem1,
        const float4* __restrict__ mem2,
        float* __restrict__ out,
        float4* __restrict__ outmem1,
        float4* __restrict__ outmem2,
        int N, int H, int KP1)
{
    const int warpsPerBlock = blockDim.x >> 5;
    const int warpInBlock   = threadIdx.x >> 5;
    const int lane          = threadIdx.x & 31;
    const int gwarp         = blockIdx.x * warpsPerBlock + warpInBlock;
    const int totalWarps    = gridDim.x * warpsPerBlock;

    // lane's result slot: q = bit2<<2 | bit3<<1 | bit4
    const int q  = ((lane >> 4) & 1) | (((lane >> 3) & 1) << 1) | (((lane >> 2) & 1) << 2);
    const int qe = q >> 1;        // entry slot 0..3
    const int qo = q & 1;         // 0 -> out_v1, 1 -> out_v2
    const bool rep = ((lane & 3) == 0);

    float local0 = 0.0f, local1 = 0.0f;

    for (int r = gwarp; r < N; r += totalWarps) {
        // single DRAM read of the row pair; serves copy AND all dots
        const float4 m1 = mem1[(size_t)r * 32 + lane];
        const float4 m2 = mem2[(size_t)r * 32 + lane];

        // copy-through (evict-first stores)
        __stcs(&outmem1[(size_t)r * 32 + lane], m1);
        __stcs(&outmem2[(size_t)r * 32 + lane], m2);

        const int cnt = min(d_count[r], CAP);

        for (int j = 0; j < cnt; j += 4) {
            const int4 pk = *reinterpret_cast<const int4*>(
                                &d_ell[(size_t)r * CAP + j]);

            float v0, v1p, v2p, v3, v4p, v5, v6, v7;
            {
                const int b = pk.x >> 13;
                const float4 x1 = __ldg(&v1[(size_t)b * 32 + lane]);
                const float4 x2 = __ldg(&v2[(size_t)b * 32 + lane]);
                v0  = m2.x * x1.x + m2.y * x1.y + m2.z * x1.z + m2.w * x1.w; // -> out_v1
                v1p = m1.x * x2.x + m1.y * x2.y + m1.z * x2.z + m1.w * x2.w; // -> out_v2
            }
            {
                const int b = ((j + 1 < cnt) ? pk.y : pk.x) >> 13;
                const float4 x1 = __ldg(&v1[(size_t)b * 32 + lane]);
                const float4 x2 = __ldg(&v2[(size_t)b * 32 + lane]);
                v2p = m2.x * x1.x + m2.y * x1.y + m2.z * x1.z + m2.w * x1.w;
                v3  = m1.x * x2.x + m1.y * x2.y + m1.z * x2.z + m1.w * x2.w;
            }
            {
                const int b = ((j + 2 < cnt) ? pk.z : pk.x) >> 13;
                const float4 x1 = __ldg(&v1[(size_t)b * 32 + lane]);
                const float4 x2 = __ldg(&v2[(size_t)b * 32 + lane]);
                v4p = m2.x * x1.x + m2.y * x1.y + m2.z * x1.z + m2.w * x1.w;
                v5  = m1.x * x2.x + m1.y * x2.y + m1.z * x2.z + m1.w * x2.w;
            }
            {
                const int b = ((j + 3 < cnt) ? pk.w : pk.x) >> 13;
                const float4 x1 = __ldg(&v1[(size_t)b * 32 + lane]);
                const float4 x2 = __ldg(&v2[(size_t)b * 32 + lane]);
                v6  = m2.x * x1.x + m2.y * x1.y + m2.z * x1.z + m2.w * x1.w;
                v7  = m1.x * x2.x + m1.y * x2.y + m1.z * x2.z + m1.w * x2.w;
            }

            // 8-value pack-and-butterfly: 16 SHFL + 7 SEL
            v0  += __shfl_xor_sync(0xffffffffu, v0,  16);
            v1p += __shfl_xor_sync(0xffffffffu, v1p, 16);
            v2p += __shfl_xor_sync(0xffffffffu, v2p, 16);
            v3  += __shfl_xor_sync(0xffffffffu, v3,  16);
            v4p += __shfl_xor_sync(0xffffffffu, v4p, 16);
            v5  += __shfl_xor_sync(0xffffffffu, v5,  16);
            v6  += __shfl_xor_sync(0xffffffffu, v6,  16);
            v7  += __shfl_xor_sync(0xffffffffu, v7,  16);

            float w0 = (lane & 16) ? v1p : v0;
            float w1 = (lane & 16) ? v3  : v2p;
            float w2 = (lane & 16) ? v5  : v4p;
            float w3 = (lane & 16) ? v7  : v6;
            w0 += __shfl_xor_sync(0xffffffffu, w0, 8);
            w1 += __shfl_xor_sync(0xffffffffu, w1, 8);
            w2 += __shfl_xor_sync(0xffffffffu, w2, 8);
            w3 += __shfl_xor_sync(0xffffffffu, w3, 8);

            float u0 = (lane & 8) ? w1 : w0;
            float u1 = (lane & 8) ? w3 : w2;
            u0 += __shfl_xor_sync(0xffffffffu, u0, 4);
            u1 += __shfl_xor_sync(0xffffffffu, u1, 4);

            float t = (lane & 4) ? u1 : u0;
            t += __shfl_xor_sync(0xffffffffu, t, 2);
            t += __shfl_xor_sync(0xffffffffu, t, 1);

            const float ex = __expf(t * T_INV);

            if (rep && (j + qe) < cnt) {
                const int p  = (qe == 0) ? pk.x : (qe == 1) ? pk.y
                             : (qe == 2) ? pk.z : pk.w;
                const int d2 = (p >> 13) * KP1 + (p & 8191);
                __stcs(&out[qo ? (H + d2) : d2], ex);
                if (qo) local1 += ex; else local0 += ex;
            }
        }
    }

    // overflow entries (expected: none) — direct full-warp gather path
    const int novf = min(d_ovf_cnt, MAX_OVF);
    for (int o = gwarp; o < novf; o += totalWarps) {
        const int p  = d_ovf[o];
        const int b  = p >> 13;
        const int d2 = b * KP1 + (p & 8191);
        const int rr = __ldg(&idx[d2]);

        const float4 a1 = mem1[(size_t)rr * 32 + lane];
        const float4 a2 = mem2[(size_t)rr * 32 + lane];
        const float4 x1 = __ldg(&v1[(size_t)b * 32 + lane]);
        const float4 x2 = __ldg(&v2[(size_t)b * 32 + lane]);

        float s1 = a1.x * x2.x + a1.y * x2.y + a1.z * x2.z + a1.w * x2.w;
        float s2 = a2.x * x1.x + a2.y * x1.y + a2.z * x1.z + a2.w * x1.w;
        #pragma unroll
        for (int qq = 16; qq > 0; qq >>= 1) {
            s1 += __shfl_xor_sync(0xffffffffu, s1, qq);
            s2 += __shfl_xor_sync(0xffffffffu, s2, qq);
        }
        if (lane == 0) {
            const float e2 = __expf(s2 * T_INV);
            const float e1 = __expf(s1 * T_INV);
            __stcs(&out[d2], e2);
            __stcs(&out[H + d2], e1);
            local0 += e2;
            local1 += e1;
        }
    }

    // block reduce -> one double atomic per block per half
    #pragma unroll
    for (int o = 16; o > 0; o >>= 1) {
        local0 += __shfl_xor_sync(0xffffffffu, local0, o);
        local1 += __shfl_xor_sync(0xffffffffu, local1, o);
    }
    __shared__ float sh0[8], sh1[8];
    if (lane == 0) { sh0[warpInBlock] = local0; sh1[warpInBlock] = local1; }
    __syncthreads();
    if (threadIdx.x == 0) {
        float a = 0.0f, b = 0.0f;
        for (int w = 0; w < warpsPerBlock; ++w) { a += sh0[w]; b += sh1[w]; }
        atomicAdd(&g_sum[0], (double)a);
        atomicAdd(&g_sum[1], (double)b);
    }
}

// k3: lean finish — grid-stride scale, momentum update, state re-zero.
#define FIN_SCALE_BLOCKS 444
#define FIN_ZERO_BLOCKS  128
__global__ void __launch_bounds__(256) finish_kernel(
        float4* __restrict__ out4,
        int Hv2, int Hv,
        int H, long long Nll, int N,
        const float* __restrict__ v1,
        const float* __restrict__ v2,
        const float* __restrict__ mem1,
        const float* __restrict__ mem2,
        const int*   __restrict__ y,
        float* __restrict__ outmem1,
        float* __restrict__ outmem2,
        int B)
{
    const int bx = (int)blockIdx.x;

    if (bx < FIN_SCALE_BLOCKS) {
        const int stride = FIN_SCALE_BLOCKS * blockDim.x;
        const float sc0 = (float)((double)H / (g_sum[0] * (double)Nll));
        const float sc1 = (float)((double)H / (g_sum[1] * (double)Nll));
        for (int i = bx * blockDim.x + threadIdx.x; i < Hv2; i += stride) {
            const float scale = (i < Hv) ? sc0 : sc1;
            float4 v = out4[i];
            v.x *= scale; v.y *= scale; v.z *= scale; v.w *= scale;
            out4[i] = v;
        }
        return;
    }

    if (bx < FIN_SCALE_BLOCKS + B) {
        const int ub    = bx - FIN_SCALE_BLOCKS;
        const int which = threadIdx.x >> 7;
        const int t     = threadIdx.x & 127;
        const int lane  = threadIdx.x & 31;
        const int w128  = (threadIdx.x >> 5) & 3;

        const float* v      = which ? v2      : v1;
        const float* mem    = which ? mem2    : mem1;
        float*       outmem = which ? outmem2 : outmem1;

        const int row = __ldg(&y[ub]);
        const float u = MOM * mem[(size_t)row * 128 + t] + (1.0f - MOM) * v[(size_t)ub * 128 + t];

        float ss = u * u;
        #pragma unroll
        for (int o = 16; o > 0; o >>= 1)
            ss += __shfl_xor_sync(0xffffffffu, ss, o);

        __shared__ float sh[2][4];
        if (lane == 0) sh[which][w128] = ss;
        __syncthreads();

        const float tot = sh[which][0] + sh[which][1] + sh[which][2] + sh[which][3];
        outmem[(size_t)row * 128 + t] = u * rsqrtf(tot);
        return;
    }

    // zero-state restore (grid-stride)
    const int zb = bx - FIN_SCALE_BLOCKS - B;
    const int zstride = FIN_ZERO_BLOCKS * blockDim.x;
    for (int i = zb * blockDim.x + threadIdx.x; i < N; i += zstride)
        d_count[i] = 0;
    if (zb == 0 && threadIdx.x == 0) d_ovf_cnt = 0;
}

extern "C" void kernel_launch(void* const* d_in, const int* in_sizes, int n_in,
                              void* d_out, int out_size)
{
    const float* v1   = (const float*)d_in[0];
    const float* v2   = (const float*)d_in[1];
    const int*   idx  = (const int*)  d_in[2];
    const int*   y    = (const int*)  d_in[3];
    const float* mem1 = (const float*)d_in[4];
    const float* mem2 = (const float*)d_in[5];

    const int B   = in_sizes[3];          // 128
    const int D   = in_sizes[0] / B;      // 128
    const int KP1 = in_sizes[2] / B;      // 4097
    const int N   = in_sizes[4] / D;      // 100000
    const int H   = B * KP1;              // 524416
    const int ND  = N * D;                // 12800000

    float* out = (float*)d_out;
    float* outmem1 = out + 2 * (size_t)H;
    float* outmem2 = outmem1 + (size_t)ND;

    const float invKP1 = 1.0f / (float)KP1;

    build_kernel<<<(H + 255) / 256, 256>>>(idx, H, KP1, invKP1);

    main_kernel<<<1998, 256>>>((const float4*)v1, (const float4*)v2, idx,
                               (const float4*)mem1, (const float4*)mem2,
                               out, (float4*)outmem1, (float4*)outmem2,
                               N, H, KP1);

    const int Hv  = H / 4;
    const int Hv2 = 2 * Hv;
    finish_kernel<<<FIN_SCALE_BLOCKS + B + FIN_ZERO_BLOCKS, 256>>>(
        (float4*)d_out, Hv2, Hv, H, (long long)N, N,
        v1, v2, mem1, mem2, y, outmem1, outmem2, B);
}